// round 13
// baseline (speedup 1.0000x reference)
#include <cuda_runtime.h>
#include <cuda_fp16.h>
#include <math.h>
#include <stdint.h>

#define BATCH 32
#define SEQ   128
#define KDIM  1024
#define NCAPS 16
#define DCAPS 512
#define NDIM  8192   // NCAPS*DCAPS
#define MDIM  4096   // BATCH*SEQ
#define EPS   1e-7f

// Output layout: V (32*16*512), C_ret (3*32*128*16), B_logits (32*128*16)
#define OFF_V 0
#define OFF_C (BATCH * NCAPS * DCAPS)              // 262144
#define OFF_B (OFF_C + 3 * BATCH * SEQ * NCAPS)    // 458752

// ---------------- device scratch (no allocation allowed) -------------------
__device__ __half g_Uh[(size_t)MDIM * NDIM];     // caps_uhat fp16 (64 MiB)
__device__ float g_B[BATCH * SEQ * NCAPS];       // routing logits
__device__ float g_S[BATCH * NCAPS * DCAPS];     // S accumulator
__device__ float g_V[BATCH * NCAPS * DCAPS];     // V per iteration
__device__ __half g_Ah[(size_t)MDIM * KDIM];     // x fp16 [M,K]
__device__ __half g_Wh[(size_t)NDIM * KDIM];     // W^T fp16 [N,K]

// ---------------- PTX helpers (baseline ISA only) ---------------------------
__device__ __forceinline__ uint32_t smem_u32(const void* p) {
  uint32_t a;
  asm("{ .reg .u64 t; cvta.to.shared.u64 t, %1; cvt.u32.u64 %0, t; }"
      : "=r"(a) : "l"(p));
  return a;
}
__device__ __forceinline__ void cp16(uint32_t s, const void* g) {
  asm volatile("cp.async.cg.shared.global [%0], [%1], 16;" :: "r"(s), "l"(g));
}
#define CP_COMMIT() asm volatile("cp.async.commit_group;" ::: "memory")
#define CP_WAIT(n)  asm volatile("cp.async.wait_group %0;" :: "n"(n) : "memory")

#define LDSM_X4(r, a)                                                         \
  asm volatile("ldmatrix.sync.aligned.m8n8.x4.shared.b16 {%0,%1,%2,%3}, [%4];" \
      : "=r"((r)[0]), "=r"((r)[1]), "=r"((r)[2]), "=r"((r)[3]) : "r"(a))

#define MMA16816F(d, a, b0, b1)                                               \
  asm volatile(                                                               \
      "mma.sync.aligned.m16n8k16.row.col.f32.f16.f16.f32 "                    \
      "{%0,%1,%2,%3}, {%4,%5,%6,%7}, {%8,%9}, {%0,%1,%2,%3};"                 \
      : "+f"((d)[0]), "+f"((d)[1]), "+f"((d)[2]), "+f"((d)[3])                \
      : "r"((a)[0]), "r"((a)[1]), "r"((a)[2]), "r"((a)[3]), "r"(b0), "r"(b1))

// fast tanh: Eigen-style odd rational, FMA-only + one MUFU.RCP; rel err ~1e-7
__device__ __forceinline__ float fast_tanh(float x) {
  float xc = fminf(fmaxf(x, -7.90531110763549805f), 7.90531110763549805f);
  float x2 = xc * xc;
  float p = -2.76076847742355e-16f;
  p = fmaf(p, x2, 2.00018790482477e-13f);
  p = fmaf(p, x2, -8.60467152213735e-11f);
  p = fmaf(p, x2, 5.12229709037114e-08f);
  p = fmaf(p, x2, 1.48572235717979e-05f);
  p = fmaf(p, x2, 6.37261928875436e-04f);
  p = fmaf(p, x2, 4.89352455891786e-03f);
  p = p * xc;
  float q = 1.19825839466702e-06f;
  q = fmaf(q, x2, 1.18534705686654e-04f);
  q = fmaf(q, x2, 2.26843463243900e-03f);
  q = fmaf(q, x2, 4.89352518554385e-03f);
  return __fdividef(p, q);
}

// ---------------- prep kernels ---------------------------------------------
__global__ __launch_bounds__(256) void conv_a_kernel(const float* __restrict__ x) {
  size_t i = (size_t)blockIdx.x * 256 + threadIdx.x;  // float4 index
  float4 v = ((const float4*)x)[i];
  ((__half2*)g_Ah)[2 * i] = __floats2half2_rn(v.x, v.y);
  ((__half2*)g_Ah)[2 * i + 1] = __floats2half2_rn(v.z, v.w);
}

// W [K, N] row-major -> W^T [N, K] fp16, tiled transpose
__global__ __launch_bounds__(256) void conv_wt_kernel(const float* __restrict__ W) {
  __shared__ float tile[32][33];
  int n0 = blockIdx.x * 32, k0 = blockIdx.y * 32;
  int tx = threadIdx.x, ty = threadIdx.y;  // 32 x 8
#pragma unroll
  for (int j = 0; j < 4; j++)
    tile[ty + j * 8][tx] = W[(size_t)(k0 + ty + j * 8) * NDIM + n0 + tx];
  __syncthreads();
#pragma unroll
  for (int j = 0; j < 4; j++)
    g_Wh[(size_t)(n0 + ty + j * 8) * KDIM + k0 + tx] =
        __float2half_rn(tile[tx][ty + j * 8]);
}

// C_ret[iter 0] is uniform 1/16
__global__ __launch_bounds__(256) void c0_kernel(float* __restrict__ out) {
  out[OFF_C + blockIdx.x * 256 + threadIdx.x] = 0.0625f;
}

// ---------------- fp16 HMMA GEMM + tanh -> g_Uh, fused S0 ------------------
// CTA tile 128x128, 4 warps (2x2), warp tile 64x64, BK=64, 3 smem stages.
// 128B-row swizzle: off(r,c16) = r*128 + ((c16 ^ (r&7))<<4). 16 sync points.
#define STG 32768
#define NSTAGE 3
#define GEMM_SMEM (NSTAGE * STG)   // 98304
#define NCHUNK (KDIM / 64)         // 16

__device__ __forceinline__ void load_stage(uint32_t s0, int rowBase, int colBase,
                                           int kt, int tid) {
#pragma unroll
  for (int l = 0; l < 8; l++) {
    int i = tid + l * 128;           // 0..1023
    int r = i >> 3, c = i & 7;
    uint32_t off = (uint32_t)(r * 128 + ((c ^ (r & 7)) << 4));
    cp16(s0 + off, &g_Ah[(size_t)(rowBase + r) * KDIM + kt + c * 8]);
    cp16(s0 + 16384 + off, &g_Wh[(size_t)(colBase + r) * KDIM + kt + c * 8]);
  }
}

__global__ __launch_bounds__(128, 2) void gemm_hmma_kernel() {
  extern __shared__ char smem[];
  const uint32_t sb = smem_u32(smem);
  const int tid = threadIdx.x;
  const int w = tid >> 5, lane = tid & 31;
  const int wr = w >> 1, wc = w & 1;          // 2x2 warp grid
  const int rowBase = blockIdx.y * 128;       // batch b = blockIdx.y
  const int colBase = blockIdx.x * 128;

  const int selA = (lane >> 4) & 1;
  const int selB = (lane >> 3) & 1;
  uint32_t addrA[4], addrB[4];
  int xrA[4], xrB[4];
#pragma unroll
  for (int i = 0; i < 4; i++) {
    int r = wr * 64 + i * 16 + (lane & 7) + ((lane >> 3) & 1) * 8;
    addrA[i] = (uint32_t)(r * 128);
    xrA[i] = r & 7;
  }
#pragma unroll
  for (int jj = 0; jj < 4; jj++) {
    int r = wc * 64 + jj * 16 + (lane & 7) + ((lane >> 4) & 1) * 8;
    addrB[jj] = (uint32_t)(r * 128);
    xrB[jj] = r & 7;
  }

  float acc[4][8][4];
#pragma unroll
  for (int i = 0; i < 4; i++)
#pragma unroll
    for (int j = 0; j < 8; j++)
#pragma unroll
      for (int q = 0; q < 4; q++) acc[i][j][q] = 0.f;

  load_stage(sb, rowBase, colBase, 0, tid);
  CP_COMMIT();
  load_stage(sb + STG, rowBase, colBase, 64, tid);
  CP_COMMIT();

  int st = 0;
  for (int c = 0; c < NCHUNK; c++) {
    const uint32_t s0 = sb + st * STG;
    CP_WAIT(1);
    __syncthreads();
    if (c + 2 < NCHUNK) {
      int st2 = st + 2; if (st2 >= NSTAGE) st2 -= NSTAGE;
      load_stage(sb + st2 * STG, rowBase, colBase, (c + 2) * 64, tid);
    }
    CP_COMMIT();

#pragma unroll
    for (int s = 0; s < 4; s++) {               // four k16 steps per chunk
      const int ca = 2 * s + selA;
      const int cb = 2 * s + selB;
      uint32_t a[4][4];
#pragma unroll
      for (int i = 0; i < 4; i++)
        LDSM_X4(a[i], s0 + addrA[i] + ((uint32_t)(ca ^ xrA[i]) << 4));
#pragma unroll
      for (int jj = 0; jj < 4; jj++) {
        uint32_t bh[4];
        LDSM_X4(bh, s0 + 16384 + addrB[jj] + ((uint32_t)(cb ^ xrB[jj]) << 4));
#pragma unroll
        for (int i = 0; i < 4; i++) {
          MMA16816F(acc[i][jj * 2],     a[i], bh[0], bh[1]);
          MMA16816F(acc[i][jj * 2 + 1], a[i], bh[2], bh[3]);
        }
      }
    }
    st++; if (st == NSTAGE) st = 0;
  }

  // ---- epilogue: tanh -> g_Uh, fused S0 column sums ----
  CP_WAIT(0);
  __syncthreads();  // all warps done with LDSM before smem reuse below
  float* sred = (float*)smem;  // [2][128]

  const int erow = rowBase + wr * 64 + (lane >> 2);
  const int ecol = colBase + wc * 64 + (lane & 3) * 2;
  float colsum[16];
#pragma unroll
  for (int k = 0; k < 16; k++) colsum[k] = 0.f;

#pragma unroll
  for (int i = 0; i < 4; i++) {
#pragma unroll
    for (int j = 0; j < 8; j++) {
      float t0 = fast_tanh(acc[i][j][0]);
      float t1 = fast_tanh(acc[i][j][1]);
      float t2 = fast_tanh(acc[i][j][2]);
      float t3 = fast_tanh(acc[i][j][3]);
      colsum[j * 2]     += t0 + t2;
      colsum[j * 2 + 1] += t1 + t3;
      *(__half2*)&g_Uh[(size_t)(erow + i * 16) * NDIM + ecol + j * 8] =
          __floats2half2_rn(t0, t1);
      *(__half2*)&g_Uh[(size_t)(erow + i * 16 + 8) * NDIM + ecol + j * 8] =
          __floats2half2_rn(t2, t3);
    }
  }
  // reduce over the warp's 8 row-groups (lanes with same lane&3)
#pragma unroll
  for (int o = 4; o <= 16; o <<= 1)
#pragma unroll
    for (int k = 0; k < 16; k++)
      colsum[k] += __shfl_xor_sync(0xffffffffu, colsum[k], o);
  if (lane < 4) {
#pragma unroll
    for (int j = 0; j < 8; j++) {
      sred[wr * 128 + wc * 64 + j * 8 + lane * 2]     = colsum[j * 2];
      sred[wr * 128 + wc * 64 + j * 8 + lane * 2 + 1] = colsum[j * 2 + 1];
    }
  }
  __syncthreads();
  if (tid < 128) {
    const int ncap = colBase >> 9;       // capsule (tile never spans capsules)
    const int d0 = colBase & 511;
    g_S[((size_t)(blockIdx.y * NCAPS + ncap)) * DCAPS + d0 + tid] =
        (sred[tid] + sred[128 + tid]) * 0.0625f;
  }
}

// ---------------- fused routing pass (warp-autonomous, iters 1 & 2) --------
__global__ __launch_bounds__(256) void pass_kernel(float* __restrict__ out,
                                                   int iter) {
  const int b = blockIdx.x >> 4;
  const int sc = blockIdx.x & 15;
  const int tid = threadIdx.x;
  const int lane = tid & 31;
  const int w = tid >> 5;
  const int s0 = sc * 8;

  __shared__ __align__(16) float Vsh[NCAPS * DCAPS];  // 32 KB
  __shared__ float csh[8][NCAPS];

  {
    const float4* vsrc = (const float4*)&g_V[(size_t)b * NCAPS * DCAPS];
    float4* vdst = (float4*)Vsh;
#pragma unroll
    for (int j = 0; j < 8; j++) vdst[tid + j * 256] = vsrc[tid + j * 256];
    __syncthreads();
  }

  // ---- phase 1: warp w -> row s ----
  const int s = s0 + w;
  {
    const __half* Us = &g_Uh[(size_t)(b * SEQ + s) * NDIM];
    float bv = 0.f;
#pragma unroll 4
    for (int n = 0; n < NCAPS; n++) {
      const uint2* up = (const uint2*)(Us + n * DCAPS);
      float d = 0.f;
#pragma unroll
      for (int j = 0; j < 4; j++) {
        uint2 hv = up[lane + j * 32];  // halves at d = lane*4 + j*128
        float2 f0 = __half22float2(*(__half2*)&hv.x);
        float2 f1 = __half22float2(*(__half2*)&hv.y);
        const float4 vv = *(const float4*)&Vsh[n * DCAPS + lane * 4 + j * 128];
        d = fmaf(f0.x, vv.x, d);
        d = fmaf(f0.y, vv.y, d);
        d = fmaf(f1.x, vv.z, d);
        d = fmaf(f1.y, vv.w, d);
      }
#pragma unroll
      for (int o = 16; o > 0; o >>= 1) d += __shfl_xor_sync(0xffffffffu, d, o);
      if (lane == n) bv = d;
    }
    const int bi0 = (b * SEQ + s) * NCAPS;
    float bfull = -1e30f;
    if (lane < NCAPS) {
      bfull = bv + (iter == 2 ? g_B[bi0 + lane] : 0.f);
      if (iter == 1) g_B[bi0 + lane] = bfull;
      else out[OFF_B + bi0 + lane] = bfull;  // B_logits = B entering last iter
    }
    float mx = bfull;
#pragma unroll
    for (int o = 8; o > 0; o >>= 1) mx = fmaxf(mx, __shfl_xor_sync(0xffffffffu, mx, o));
    float e = (lane < NCAPS) ? expf(bfull - mx) : 0.f;
    float sum = e;
#pragma unroll
    for (int o = 8; o > 0; o >>= 1) sum += __shfl_xor_sync(0xffffffffu, sum, o);
    if (lane < NCAPS) {
      float cc = e / sum;
      csh[w][lane] = cc;
      out[OFF_C + (size_t)((iter * BATCH + b) * SEQ + s) * NCAPS + lane] = cc;
    }
  }
  __syncthreads();

  // ---- phase 2: warp w -> capsules w and w+8 ----
#pragma unroll
  for (int half = 0; half < 2; half++) {
    const int n = w + half * 8;
    float Sacc[16];
#pragma unroll
    for (int q = 0; q < 16; q++) Sacc[q] = 0.f;
#pragma unroll
    for (int r = 0; r < 8; r++) {
      const float cc = csh[r][n];
      const uint2* up =
          (const uint2*)&g_Uh[((size_t)(b * SEQ + s0 + r) * NCAPS + n) * DCAPS];
#pragma unroll
      for (int j = 0; j < 4; j++) {
        uint2 hv = up[lane + j * 32];
        float2 f0 = __half22float2(*(__half2*)&hv.x);
        float2 f1 = __half22float2(*(__half2*)&hv.y);
        Sacc[j * 4 + 0] = fmaf(cc, f0.x, Sacc[j * 4 + 0]);
        Sacc[j * 4 + 1] = fmaf(cc, f0.y, Sacc[j * 4 + 1]);
        Sacc[j * 4 + 2] = fmaf(cc, f1.x, Sacc[j * 4 + 2]);
        Sacc[j * 4 + 3] = fmaf(cc, f1.y, Sacc[j * 4 + 3]);
      }
    }
    float* Sg = &g_S[(size_t)(b * NCAPS + n) * DCAPS];
#pragma unroll
    for (int j = 0; j < 4; j++)
#pragma unroll
      for (int q = 0; q < 4; q++)
        atomicAdd(&Sg[lane * 4 + j * 128 + q], Sacc[j * 4 + q]);
  }
}

// squash: V = S / sqrt(||S||^2 + eps); re-zero S (keeps steady state zero)
__global__ __launch_bounds__(512) void squash_kernel(float* __restrict__ out,
                                                     int last) {
  const int bn = blockIdx.x;  // (b*16+n)
  const int tid = threadIdx.x;
  const int lane = tid & 31, warp = tid >> 5;
  __shared__ float wred[16];
  __shared__ float s_inv;

  size_t base = (size_t)bn * DCAPS;
  float s = g_S[base + tid];
  g_S[base + tid] = 0.f;
  float sq = s * s;
#pragma unroll
  for (int o = 16; o > 0; o >>= 1) sq += __shfl_xor_sync(0xffffffffu, sq, o);
  if (lane == 0) wred[warp] = sq;
  __syncthreads();
  if (tid == 0) {
    float t = 0.f;
#pragma unroll
    for (int k = 0; k < 16; k++) t += wred[k];
    s_inv = 1.0f / sqrtf(t + EPS);
  }
  __syncthreads();
  float v = s * s_inv;
  g_V[base + tid] = v;
  if (last) out[OFF_V + base + tid] = v;
}

// ---------------------------------------------------------------------------
extern "C" void kernel_launch(void* const* d_in, const int* in_sizes, int n_in,
                              void* d_out, int out_size) {
  const float* x = (const float*)d_in[0];  // (32,128,1024) f32
  const float* W = (const float*)d_in[1];  // (1024,8192) f32
  float* out = (float*)d_out;

  cudaFuncSetAttribute(gemm_hmma_kernel,
                       cudaFuncAttributeMaxDynamicSharedMemorySize, GEMM_SMEM);

  conv_a_kernel<<<MDIM * KDIM / (256 * 4), 256>>>(x);
  conv_wt_kernel<<<dim3(NDIM / 32, KDIM / 32), dim3(32, 8)>>>(W);
  c0_kernel<<<BATCH * SEQ * NCAPS / 256, 256>>>(out);
  gemm_hmma_kernel<<<dim3(NDIM / 128, MDIM / 128), 128, GEMM_SMEM>>>();

  squash_kernel<<<BATCH * NCAPS, 512>>>(out, 0);   // V0 from fused S0
  pass_kernel<<<BATCH * 16, 256>>>(out, 1);
  squash_kernel<<<BATCH * NCAPS, 512>>>(out, 0);
  pass_kernel<<<BATCH * 16, 256>>>(out, 2);
  squash_kernel<<<BATCH * NCAPS, 512>>>(out, 1);
}

// round 14
// speedup vs baseline: 1.0111x; 1.0111x over previous
#include <cuda_runtime.h>
#include <cuda_fp16.h>
#include <math.h>
#include <stdint.h>

#define BATCH 32
#define SEQ   128
#define KDIM  1024
#define NCAPS 16
#define DCAPS 512
#define NDIM  8192   // NCAPS*DCAPS
#define MDIM  4096   // BATCH*SEQ
#define EPS   1e-7f

// Output layout: V (32*16*512), C_ret (3*32*128*16), B_logits (32*128*16)
#define OFF_V 0
#define OFF_C (BATCH * NCAPS * DCAPS)              // 262144
#define OFF_B (OFF_C + 3 * BATCH * SEQ * NCAPS)    // 458752

// ---------------- device scratch (no allocation allowed) -------------------
__device__ __half g_Uh[(size_t)MDIM * NDIM];     // caps_uhat fp16 (64 MiB)
__device__ float g_B[BATCH * SEQ * NCAPS];       // routing logits
__device__ float g_S[BATCH * NCAPS * DCAPS];     // S accumulator
__device__ float g_V[BATCH * NCAPS * DCAPS];     // V per iteration
__device__ __half g_Ah[(size_t)MDIM * KDIM];     // x fp16 [M,K]
__device__ __half g_Wh[(size_t)NDIM * KDIM];     // W^T fp16 [N,K]

// ---------------- PTX helpers (baseline ISA only) ---------------------------
__device__ __forceinline__ uint32_t smem_u32(const void* p) {
  uint32_t a;
  asm("{ .reg .u64 t; cvta.to.shared.u64 t, %1; cvt.u32.u64 %0, t; }"
      : "=r"(a) : "l"(p));
  return a;
}
__device__ __forceinline__ void cp16(uint32_t s, const void* g) {
  asm volatile("cp.async.cg.shared.global [%0], [%1], 16;" :: "r"(s), "l"(g));
}
#define CP_COMMIT() asm volatile("cp.async.commit_group;" ::: "memory")
#define CP_WAIT(n)  asm volatile("cp.async.wait_group %0;" :: "n"(n) : "memory")

#define LDSM_X4(r, a)                                                         \
  asm volatile("ldmatrix.sync.aligned.m8n8.x4.shared.b16 {%0,%1,%2,%3}, [%4];" \
      : "=r"((r)[0]), "=r"((r)[1]), "=r"((r)[2]), "=r"((r)[3]) : "r"(a))

#define MMA16816F(d, a, b0, b1)                                               \
  asm volatile(                                                               \
      "mma.sync.aligned.m16n8k16.row.col.f32.f16.f16.f32 "                    \
      "{%0,%1,%2,%3}, {%4,%5,%6,%7}, {%8,%9}, {%0,%1,%2,%3};"                 \
      : "+f"((d)[0]), "+f"((d)[1]), "+f"((d)[2]), "+f"((d)[3])                \
      : "r"((a)[0]), "r"((a)[1]), "r"((a)[2]), "r"((a)[3]), "r"(b0), "r"(b1))

// fast tanh: Eigen-style odd rational, FMA-only + one MUFU.RCP; rel err ~1e-7
__device__ __forceinline__ float fast_tanh(float x) {
  float xc = fminf(fmaxf(x, -7.90531110763549805f), 7.90531110763549805f);
  float x2 = xc * xc;
  float p = -2.76076847742355e-16f;
  p = fmaf(p, x2, 2.00018790482477e-13f);
  p = fmaf(p, x2, -8.60467152213735e-11f);
  p = fmaf(p, x2, 5.12229709037114e-08f);
  p = fmaf(p, x2, 1.48572235717979e-05f);
  p = fmaf(p, x2, 6.37261928875436e-04f);
  p = fmaf(p, x2, 4.89352455891786e-03f);
  p = p * xc;
  float q = 1.19825839466702e-06f;
  q = fmaf(q, x2, 1.18534705686654e-04f);
  q = fmaf(q, x2, 2.26843463243900e-03f);
  q = fmaf(q, x2, 4.89352518554385e-03f);
  return __fdividef(p, q);
}

// ---------------- prep kernels ---------------------------------------------
__global__ __launch_bounds__(256) void conv_a_kernel(const float* __restrict__ x) {
  size_t i = (size_t)blockIdx.x * 256 + threadIdx.x;  // float4 index
  float4 v = ((const float4*)x)[i];
  ((__half2*)g_Ah)[2 * i] = __floats2half2_rn(v.x, v.y);
  ((__half2*)g_Ah)[2 * i + 1] = __floats2half2_rn(v.z, v.w);
}

// W [K, N] row-major -> W^T [N, K] fp16, tiled transpose
__global__ __launch_bounds__(256) void conv_wt_kernel(const float* __restrict__ W) {
  __shared__ float tile[32][33];
  int n0 = blockIdx.x * 32, k0 = blockIdx.y * 32;
  int tx = threadIdx.x, ty = threadIdx.y;  // 32 x 8
#pragma unroll
  for (int j = 0; j < 4; j++)
    tile[ty + j * 8][tx] = W[(size_t)(k0 + ty + j * 8) * NDIM + n0 + tx];
  __syncthreads();
#pragma unroll
  for (int j = 0; j < 4; j++)
    g_Wh[(size_t)(n0 + ty + j * 8) * KDIM + k0 + tx] =
        __float2half_rn(tile[tx][ty + j * 8]);
}

// C_ret[iter 0] is uniform 1/16
__global__ __launch_bounds__(256) void c0_kernel(float* __restrict__ out) {
  out[OFF_C + blockIdx.x * 256 + threadIdx.x] = 0.0625f;
}

// ---------------- fp16 HMMA GEMM + tanh -> g_Uh, fused S0 ------------------
// CTA tile 128x128, 4 warps (2x2), warp tile 64x64, BK=64, 3 smem stages.
// B fragments explicitly double-buffered (ptxas has no reg headroom to do it).
#define STG 32768
#define NSTAGE 3
#define GEMM_SMEM (NSTAGE * STG)   // 98304
#define NCHUNK (KDIM / 64)         // 16

__device__ __forceinline__ void load_stage(uint32_t s0, int rowBase, int colBase,
                                           int kt, int tid) {
#pragma unroll
  for (int l = 0; l < 8; l++) {
    int i = tid + l * 128;           // 0..1023
    int r = i >> 3, c = i & 7;
    uint32_t off = (uint32_t)(r * 128 + ((c ^ (r & 7)) << 4));
    cp16(s0 + off, &g_Ah[(size_t)(rowBase + r) * KDIM + kt + c * 8]);
    cp16(s0 + 16384 + off, &g_Wh[(size_t)(colBase + r) * KDIM + kt + c * 8]);
  }
}

__global__ __launch_bounds__(128, 2) void gemm_hmma_kernel() {
  extern __shared__ char smem[];
  const uint32_t sb = smem_u32(smem);
  const int tid = threadIdx.x;
  const int w = tid >> 5, lane = tid & 31;
  const int wr = w >> 1, wc = w & 1;          // 2x2 warp grid
  const int rowBase = blockIdx.y * 128;       // batch b = blockIdx.y
  const int colBase = blockIdx.x * 128;

  const int selA = (lane >> 4) & 1;
  const int selB = (lane >> 3) & 1;
  uint32_t addrA[4], addrB[4];
  int xrA[4], xrB[4];
#pragma unroll
  for (int i = 0; i < 4; i++) {
    int r = wr * 64 + i * 16 + (lane & 7) + ((lane >> 3) & 1) * 8;
    addrA[i] = (uint32_t)(r * 128);
    xrA[i] = r & 7;
  }
#pragma unroll
  for (int jj = 0; jj < 4; jj++) {
    int r = wc * 64 + jj * 16 + (lane & 7) + ((lane >> 4) & 1) * 8;
    addrB[jj] = (uint32_t)(r * 128);
    xrB[jj] = r & 7;
  }

  float acc[4][8][4];
#pragma unroll
  for (int i = 0; i < 4; i++)
#pragma unroll
    for (int j = 0; j < 8; j++)
#pragma unroll
      for (int q = 0; q < 4; q++) acc[i][j][q] = 0.f;

  load_stage(sb, rowBase, colBase, 0, tid);
  CP_COMMIT();
  load_stage(sb + STG, rowBase, colBase, 64, tid);
  CP_COMMIT();

  int st = 0;
  for (int c = 0; c < NCHUNK; c++) {
    const uint32_t s0 = sb + st * STG;
    CP_WAIT(1);
    __syncthreads();
    if (c + 2 < NCHUNK) {
      int st2 = st + 2; if (st2 >= NSTAGE) st2 -= NSTAGE;
      load_stage(sb + st2 * STG, rowBase, colBase, (c + 2) * 64, tid);
    }
    CP_COMMIT();

#pragma unroll
    for (int s = 0; s < 4; s++) {               // four k16 steps per chunk
      const int ca = 2 * s + selA;
      const int cb = 2 * s + selB;
      uint32_t a[4][4];
#pragma unroll
      for (int i = 0; i < 4; i++)
        LDSM_X4(a[i], s0 + addrA[i] + ((uint32_t)(ca ^ xrA[i]) << 4));
      uint32_t b2[2][4];
      LDSM_X4(b2[0], s0 + 16384 + addrB[0] + ((uint32_t)(cb ^ xrB[0]) << 4));
#pragma unroll
      for (int jj = 0; jj < 4; jj++) {
        if (jj < 3)
          LDSM_X4(b2[(jj + 1) & 1],
                  s0 + 16384 + addrB[jj + 1] + ((uint32_t)(cb ^ xrB[jj + 1]) << 4));
        const uint32_t* bh = b2[jj & 1];
#pragma unroll
        for (int i = 0; i < 4; i++) {
          MMA16816F(acc[i][jj * 2],     a[i], bh[0], bh[1]);
          MMA16816F(acc[i][jj * 2 + 1], a[i], bh[2], bh[3]);
        }
      }
    }
    st++; if (st == NSTAGE) st = 0;
  }

  // ---- epilogue: tanh -> g_Uh, fused S0 column sums ----
  CP_WAIT(0);
  __syncthreads();  // all warps done with LDSM before smem reuse below
  float* sred = (float*)smem;  // [2][128]

  const int erow = rowBase + wr * 64 + (lane >> 2);
  const int ecol = colBase + wc * 64 + (lane & 3) * 2;
  float colsum[16];
#pragma unroll
  for (int k = 0; k < 16; k++) colsum[k] = 0.f;

#pragma unroll
  for (int i = 0; i < 4; i++) {
#pragma unroll
    for (int j = 0; j < 8; j++) {
      float t0 = fast_tanh(acc[i][j][0]);
      float t1 = fast_tanh(acc[i][j][1]);
      float t2 = fast_tanh(acc[i][j][2]);
      float t3 = fast_tanh(acc[i][j][3]);
      colsum[j * 2]     += t0 + t2;
      colsum[j * 2 + 1] += t1 + t3;
      *(__half2*)&g_Uh[(size_t)(erow + i * 16) * NDIM + ecol + j * 8] =
          __floats2half2_rn(t0, t1);
      *(__half2*)&g_Uh[(size_t)(erow + i * 16 + 8) * NDIM + ecol + j * 8] =
          __floats2half2_rn(t2, t3);
    }
  }
  // reduce over the warp's 8 row-groups (lanes with same lane&3)
#pragma unroll
  for (int o = 4; o <= 16; o <<= 1)
#pragma unroll
    for (int k = 0; k < 16; k++)
      colsum[k] += __shfl_xor_sync(0xffffffffu, colsum[k], o);
  if (lane < 4) {
#pragma unroll
    for (int j = 0; j < 8; j++) {
      sred[wr * 128 + wc * 64 + j * 8 + lane * 2]     = colsum[j * 2];
      sred[wr * 128 + wc * 64 + j * 8 + lane * 2 + 1] = colsum[j * 2 + 1];
    }
  }
  __syncthreads();
  if (tid < 128) {
    const int ncap = colBase >> 9;       // capsule (tile never spans capsules)
    const int d0 = colBase & 511;
    g_S[((size_t)(blockIdx.y * NCAPS + ncap)) * DCAPS + d0 + tid] =
        (sred[tid] + sred[128 + tid]) * 0.0625f;
  }
}

// ---------------- fused routing pass (512 threads, iters 1 & 2) ------------
// CTA per (b, s-chunk of 8), 16 warps.
// Phase 1: warps (r, hl): row r = w&7, capsules hl*8..hl*8+7 -> dsh.
// Softmax: warps 0..7 handle row w, lanes 0..15.
// Phase 2: warp w -> capsule w.
__global__ __launch_bounds__(512) void pass_kernel(float* __restrict__ out,
                                                   int iter) {
  const int b = blockIdx.x >> 4;
  const int sc = blockIdx.x & 15;
  const int tid = threadIdx.x;
  const int lane = tid & 31;
  const int w = tid >> 5;
  const int s0 = sc * 8;

  __shared__ __align__(16) float Vsh[NCAPS * DCAPS];  // 32 KB
  __shared__ float csh[8][NCAPS];
  __shared__ float dsh[8][NCAPS];

  {
    const float4* vsrc = (const float4*)&g_V[(size_t)b * NCAPS * DCAPS];
    float4* vdst = (float4*)Vsh;
#pragma unroll
    for (int j = 0; j < 4; j++) vdst[tid + j * 512] = vsrc[tid + j * 512];
    __syncthreads();
  }

  // ---- phase 1: warp (r, hl) computes 8 dots for row s0+r ----
  {
    const int r = w & 7;
    const int hl = w >> 3;
    const __half* Us = &g_Uh[(size_t)(b * SEQ + s0 + r) * NDIM];
#pragma unroll
    for (int k = 0; k < 8; k++) {
      const int n = hl * 8 + k;
      const uint2* up = (const uint2*)(Us + n * DCAPS);
      float d = 0.f;
#pragma unroll
      for (int j = 0; j < 4; j++) {
        uint2 hv = up[lane + j * 32];  // halves at d = lane*4 + j*128
        float2 f0 = __half22float2(*(__half2*)&hv.x);
        float2 f1 = __half22float2(*(__half2*)&hv.y);
        const float4 vv = *(const float4*)&Vsh[n * DCAPS + lane * 4 + j * 128];
        d = fmaf(f0.x, vv.x, d);
        d = fmaf(f0.y, vv.y, d);
        d = fmaf(f1.x, vv.z, d);
        d = fmaf(f1.y, vv.w, d);
      }
#pragma unroll
      for (int o = 16; o > 0; o >>= 1) d += __shfl_xor_sync(0xffffffffu, d, o);
      if (lane == 0) dsh[r][n] = d;
    }
  }
  __syncthreads();

  // ---- softmax: warps 0..7, row w, lanes 0..15 ----
  if (w < 8) {
    const int s = s0 + w;
    const int bi0 = (b * SEQ + s) * NCAPS;
    float bfull = -1e30f;
    if (lane < NCAPS) {
      bfull = dsh[w][lane] + (iter == 2 ? g_B[bi0 + lane] : 0.f);
      if (iter == 1) g_B[bi0 + lane] = bfull;
      else out[OFF_B + bi0 + lane] = bfull;  // B_logits = B entering last iter
    }
    float mx = bfull;
#pragma unroll
    for (int o = 8; o > 0; o >>= 1) mx = fmaxf(mx, __shfl_xor_sync(0xffffffffu, mx, o));
    float e = (lane < NCAPS) ? expf(bfull - mx) : 0.f;
    float sum = e;
#pragma unroll
    for (int o = 8; o > 0; o >>= 1) sum += __shfl_xor_sync(0xffffffffu, sum, o);
    if (lane < NCAPS) {
      float cc = e / sum;
      csh[w][lane] = cc;
      out[OFF_C + (size_t)((iter * BATCH + b) * SEQ + s) * NCAPS + lane] = cc;
    }
  }
  __syncthreads();

  // ---- phase 2: warp w -> capsule w ----
  {
    const int n = w;
    float Sacc[16];
#pragma unroll
    for (int q = 0; q < 16; q++) Sacc[q] = 0.f;
#pragma unroll
    for (int r = 0; r < 8; r++) {
      const float cc = csh[r][n];
      const uint2* up =
          (const uint2*)&g_Uh[((size_t)(b * SEQ + s0 + r) * NCAPS + n) * DCAPS];
#pragma unroll
      for (int j = 0; j < 4; j++) {
        uint2 hv = up[lane + j * 32];
        float2 f0 = __half22float2(*(__half2*)&hv.x);
        float2 f1 = __half22float2(*(__half2*)&hv.y);
        Sacc[j * 4 + 0] = fmaf(cc, f0.x, Sacc[j * 4 + 0]);
        Sacc[j * 4 + 1] = fmaf(cc, f0.y, Sacc[j * 4 + 1]);
        Sacc[j * 4 + 2] = fmaf(cc, f1.x, Sacc[j * 4 + 2]);
        Sacc[j * 4 + 3] = fmaf(cc, f1.y, Sacc[j * 4 + 3]);
      }
    }
    float* Sg = &g_S[(size_t)(b * NCAPS + n) * DCAPS];
#pragma unroll
    for (int j = 0; j < 4; j++)
#pragma unroll
      for (int q = 0; q < 4; q++)
        atomicAdd(&Sg[lane * 4 + j * 128 + q], Sacc[j * 4 + q]);
  }
}

// squash: V = S / sqrt(||S||^2 + eps); re-zero S (keeps steady state zero)
__global__ __launch_bounds__(512) void squash_kernel(float* __restrict__ out,
                                                     int last) {
  const int bn = blockIdx.x;  // (b*16+n)
  const int tid = threadIdx.x;
  const int lane = tid & 31, warp = tid >> 5;
  __shared__ float wred[16];
  __shared__ float s_inv;

  size_t base = (size_t)bn * DCAPS;
  float s = g_S[base + tid];
  g_S[base + tid] = 0.f;
  float sq = s * s;
#pragma unroll
  for (int o = 16; o > 0; o >>= 1) sq += __shfl_xor_sync(0xffffffffu, sq, o);
  if (lane == 0) wred[warp] = sq;
  __syncthreads();
  if (tid == 0) {
    float t = 0.f;
#pragma unroll
    for (int k = 0; k < 16; k++) t += wred[k];
    s_inv = 1.0f / sqrtf(t + EPS);
  }
  __syncthreads();
  float v = s * s_inv;
  g_V[base + tid] = v;
  if (last) out[OFF_V + base + tid] = v;
}

// ---------------------------------------------------------------------------
extern "C" void kernel_launch(void* const* d_in, const int* in_sizes, int n_in,
                              void* d_out, int out_size) {
  const float* x = (const float*)d_in[0];  // (32,128,1024) f32
  const float* W = (const float*)d_in[1];  // (1024,8192) f32
  float* out = (float*)d_out;

  cudaFuncSetAttribute(gemm_hmma_kernel,
                       cudaFuncAttributeMaxDynamicSharedMemorySize, GEMM_SMEM);

  conv_a_kernel<<<MDIM * KDIM / (256 * 4), 256>>>(x);
  conv_wt_kernel<<<dim3(NDIM / 32, KDIM / 32), dim3(32, 8)>>>(W);
  c0_kernel<<<BATCH * SEQ * NCAPS / 256, 256>>>(out);
  gemm_hmma_kernel<<<dim3(NDIM / 128, MDIM / 128), 128, GEMM_SMEM>>>();

  squash_kernel<<<BATCH * NCAPS, 512>>>(out, 0);   // V0 from fused S0
  pass_kernel<<<BATCH * 16, 512>>>(out, 1);
  squash_kernel<<<BATCH * NCAPS, 512>>>(out, 0);
  pass_kernel<<<BATCH * 16, 512>>>(out, 2);
  squash_kernel<<<BATCH * NCAPS, 512>>>(out, 1);
}

// round 15
// speedup vs baseline: 1.0685x; 1.0568x over previous
#include <cuda_runtime.h>
#include <cuda_fp16.h>
#include <math.h>
#include <stdint.h>

#define BATCH 32
#define SEQ   128
#define KDIM  1024
#define NCAPS 16
#define DCAPS 512
#define NDIM  8192   // NCAPS*DCAPS
#define MDIM  4096   // BATCH*SEQ
#define EPS   1e-7f

// Output layout: V (32*16*512), C_ret (3*32*128*16), B_logits (32*128*16)
#define OFF_V 0
#define OFF_C (BATCH * NCAPS * DCAPS)              // 262144
#define OFF_B (OFF_C + 3 * BATCH * SEQ * NCAPS)    // 458752

// ---------------- device scratch (no allocation allowed) -------------------
__device__ __half g_Uh[(size_t)MDIM * NDIM];     // caps_uhat fp16 (64 MiB)
__device__ float g_B[BATCH * SEQ * NCAPS];       // routing logits
__device__ float g_S0[BATCH * NCAPS * DCAPS];    // S iter0 (direct store by GEMM)
__device__ float g_S1[BATCH * NCAPS * DCAPS];    // S iter1 (atomics; zero steady-state)
__device__ float g_S2[BATCH * NCAPS * DCAPS];    // S iter2 (atomics; zero steady-state)
__device__ __half g_Ah[(size_t)MDIM * KDIM];     // x fp16 [M,K]
__device__ __half g_Wh[(size_t)NDIM * KDIM];     // W^T fp16 [N,K]

// ---------------- PTX helpers (baseline ISA only) ---------------------------
__device__ __forceinline__ uint32_t smem_u32(const void* p) {
  uint32_t a;
  asm("{ .reg .u64 t; cvta.to.shared.u64 t, %1; cvt.u32.u64 %0, t; }"
      : "=r"(a) : "l"(p));
  return a;
}
__device__ __forceinline__ void cp16(uint32_t s, const void* g) {
  asm volatile("cp.async.cg.shared.global [%0], [%1], 16;" :: "r"(s), "l"(g));
}
#define CP_COMMIT() asm volatile("cp.async.commit_group;" ::: "memory")
#define CP_WAIT(n)  asm volatile("cp.async.wait_group %0;" :: "n"(n) : "memory")

#define LDSM_X4(r, a)                                                         \
  asm volatile("ldmatrix.sync.aligned.m8n8.x4.shared.b16 {%0,%1,%2,%3}, [%4];" \
      : "=r"((r)[0]), "=r"((r)[1]), "=r"((r)[2]), "=r"((r)[3]) : "r"(a))

#define MMA16816F(d, a, b0, b1)                                               \
  asm volatile(                                                               \
      "mma.sync.aligned.m16n8k16.row.col.f32.f16.f16.f32 "                    \
      "{%0,%1,%2,%3}, {%4,%5,%6,%7}, {%8,%9}, {%0,%1,%2,%3};"                 \
      : "+f"((d)[0]), "+f"((d)[1]), "+f"((d)[2]), "+f"((d)[3])                \
      : "r"((a)[0]), "r"((a)[1]), "r"((a)[2]), "r"((a)[3]), "r"(b0), "r"(b1))

// fast tanh: Eigen-style odd rational, FMA-only + one MUFU.RCP; rel err ~1e-7
__device__ __forceinline__ float fast_tanh(float x) {
  float xc = fminf(fmaxf(x, -7.90531110763549805f), 7.90531110763549805f);
  float x2 = xc * xc;
  float p = -2.76076847742355e-16f;
  p = fmaf(p, x2, 2.00018790482477e-13f);
  p = fmaf(p, x2, -8.60467152213735e-11f);
  p = fmaf(p, x2, 5.12229709037114e-08f);
  p = fmaf(p, x2, 1.48572235717979e-05f);
  p = fmaf(p, x2, 6.37261928875436e-04f);
  p = fmaf(p, x2, 4.89352455891786e-03f);
  p = p * xc;
  float q = 1.19825839466702e-06f;
  q = fmaf(q, x2, 1.18534705686654e-04f);
  q = fmaf(q, x2, 2.26843463243900e-03f);
  q = fmaf(q, x2, 4.89352518554385e-03f);
  return __fdividef(p, q);
}

// ---------------- fused prep: conv A, transpose+conv W, C0 ------------------
// blocks [0,4096): A fp32->fp16; [4096,12288): W^T; [12288,12544): C0.
__global__ __launch_bounds__(256) void prep_kernel(const float* __restrict__ x,
                                                   const float* __restrict__ W,
                                                   float* __restrict__ out) {
  const int bid = blockIdx.x;
  const int tid = threadIdx.x;
  if (bid < 4096) {
    size_t i = (size_t)bid * 256 + tid;  // float4 index
    float4 v = ((const float4*)x)[i];
    ((__half2*)g_Ah)[2 * i] = __floats2half2_rn(v.x, v.y);
    ((__half2*)g_Ah)[2 * i + 1] = __floats2half2_rn(v.z, v.w);
  } else if (bid < 12288) {
    __shared__ float tile[32][33];
    const int wid = bid - 4096;
    const int n0 = (wid & 255) * 32, k0 = (wid >> 8) * 32;
    const int tx = tid & 31, ty = tid >> 5;  // 32 x 8
#pragma unroll
    for (int j = 0; j < 4; j++)
      tile[ty + j * 8][tx] = W[(size_t)(k0 + ty + j * 8) * NDIM + n0 + tx];
    __syncthreads();
#pragma unroll
    for (int j = 0; j < 4; j++)
      g_Wh[(size_t)(n0 + ty + j * 8) * KDIM + k0 + tx] =
          __float2half_rn(tile[tx][ty + j * 8]);
  } else {
    out[OFF_C + (bid - 12288) * 256 + tid] = 0.0625f;
  }
}

// ---------------- fp16 HMMA GEMM + tanh -> g_Uh, fused S0 ------------------
// CTA tile 128x128, 4 warps (2x2), warp tile 64x64, BK=64, 3 smem stages.
#define STG 32768
#define NSTAGE 3
#define GEMM_SMEM (NSTAGE * STG)   // 98304
#define NCHUNK (KDIM / 64)         // 16

__device__ __forceinline__ void load_stage(uint32_t s0, int rowBase, int colBase,
                                           int kt, int tid) {
#pragma unroll
  for (int l = 0; l < 8; l++) {
    int i = tid + l * 128;           // 0..1023
    int r = i >> 3, c = i & 7;
    uint32_t off = (uint32_t)(r * 128 + ((c ^ (r & 7)) << 4));
    cp16(s0 + off, &g_Ah[(size_t)(rowBase + r) * KDIM + kt + c * 8]);
    cp16(s0 + 16384 + off, &g_Wh[(size_t)(colBase + r) * KDIM + kt + c * 8]);
  }
}

__global__ __launch_bounds__(128, 2) void gemm_hmma_kernel() {
  extern __shared__ char smem[];
  const uint32_t sb = smem_u32(smem);
  const int tid = threadIdx.x;
  const int w = tid >> 5, lane = tid & 31;
  const int wr = w >> 1, wc = w & 1;          // 2x2 warp grid
  const int rowBase = blockIdx.y * 128;       // batch b = blockIdx.y
  const int colBase = blockIdx.x * 128;

  const int selA = (lane >> 4) & 1;
  const int selB = (lane >> 3) & 1;
  uint32_t addrA[4], addrB[4];
  int xrA[4], xrB[4];
#pragma unroll
  for (int i = 0; i < 4; i++) {
    int r = wr * 64 + i * 16 + (lane & 7) + ((lane >> 3) & 1) * 8;
    addrA[i] = (uint32_t)(r * 128);
    xrA[i] = r & 7;
  }
#pragma unroll
  for (int jj = 0; jj < 4; jj++) {
    int r = wc * 64 + jj * 16 + (lane & 7) + ((lane >> 4) & 1) * 8;
    addrB[jj] = (uint32_t)(r * 128);
    xrB[jj] = r & 7;
  }

  float acc[4][8][4];
#pragma unroll
  for (int i = 0; i < 4; i++)
#pragma unroll
    for (int j = 0; j < 8; j++)
#pragma unroll
      for (int q = 0; q < 4; q++) acc[i][j][q] = 0.f;

  load_stage(sb, rowBase, colBase, 0, tid);
  CP_COMMIT();
  load_stage(sb + STG, rowBase, colBase, 64, tid);
  CP_COMMIT();

  int st = 0;
  for (int c = 0; c < NCHUNK; c++) {
    const uint32_t s0 = sb + st * STG;
    CP_WAIT(1);
    __syncthreads();
    if (c + 2 < NCHUNK) {
      int st2 = st + 2; if (st2 >= NSTAGE) st2 -= NSTAGE;
      load_stage(sb + st2 * STG, rowBase, colBase, (c + 2) * 64, tid);
    }
    CP_COMMIT();

#pragma unroll
    for (int s = 0; s < 4; s++) {               // four k16 steps per chunk
      const int ca = 2 * s + selA;
      const int cb = 2 * s + selB;
      uint32_t a[4][4];
#pragma unroll
      for (int i = 0; i < 4; i++)
        LDSM_X4(a[i], s0 + addrA[i] + ((uint32_t)(ca ^ xrA[i]) << 4));
      uint32_t b2[2][4];
      LDSM_X4(b2[0], s0 + 16384 + addrB[0] + ((uint32_t)(cb ^ xrB[0]) << 4));
#pragma unroll
      for (int jj = 0; jj < 4; jj++) {
        if (jj < 3)
          LDSM_X4(b2[(jj + 1) & 1],
                  s0 + 16384 + addrB[jj + 1] + ((uint32_t)(cb ^ xrB[jj + 1]) << 4));
        const uint32_t* bh = b2[jj & 1];
#pragma unroll
        for (int i = 0; i < 4; i++) {
          MMA16816F(acc[i][jj * 2],     a[i], bh[0], bh[1]);
          MMA16816F(acc[i][jj * 2 + 1], a[i], bh[2], bh[3]);
        }
      }
    }
    st++; if (st == NSTAGE) st = 0;
  }

  // ---- epilogue: tanh -> g_Uh, fused S0 column sums ----
  CP_WAIT(0);
  __syncthreads();  // all warps done with LDSM before smem reuse below
  float* sred = (float*)smem;  // [2][128]

  const int erow = rowBase + wr * 64 + (lane >> 2);
  const int ecol = colBase + wc * 64 + (lane & 3) * 2;
  float colsum[16];
#pragma unroll
  for (int k = 0; k < 16; k++) colsum[k] = 0.f;

#pragma unroll
  for (int i = 0; i < 4; i++) {
#pragma unroll
    for (int j = 0; j < 8; j++) {
      float t0 = fast_tanh(acc[i][j][0]);
      float t1 = fast_tanh(acc[i][j][1]);
      float t2 = fast_tanh(acc[i][j][2]);
      float t3 = fast_tanh(acc[i][j][3]);
      colsum[j * 2]     += t0 + t2;
      colsum[j * 2 + 1] += t1 + t3;
      *(__half2*)&g_Uh[(size_t)(erow + i * 16) * NDIM + ecol + j * 8] =
          __floats2half2_rn(t0, t1);
      *(__half2*)&g_Uh[(size_t)(erow + i * 16 + 8) * NDIM + ecol + j * 8] =
          __floats2half2_rn(t2, t3);
    }
  }
#pragma unroll
  for (int o = 4; o <= 16; o <<= 1)
#pragma unroll
    for (int k = 0; k < 16; k++)
      colsum[k] += __shfl_xor_sync(0xffffffffu, colsum[k], o);
  if (lane < 4) {
#pragma unroll
    for (int j = 0; j < 8; j++) {
      sred[wr * 128 + wc * 64 + j * 8 + lane * 2]     = colsum[j * 2];
      sred[wr * 128 + wc * 64 + j * 8 + lane * 2 + 1] = colsum[j * 2 + 1];
    }
  }
  __syncthreads();
  if (tid < 128) {
    const int ncap = colBase >> 9;       // capsule (tile never spans capsules)
    const int d0 = colBase & 511;
    g_S0[((size_t)(blockIdx.y * NCAPS + ncap)) * DCAPS + d0 + tid] =
        (sred[tid] + sred[128 + tid]) * 0.0625f;
  }
}

// ---------------- fused routing pass + in-smem squash ----------------------
// 512 threads, CTA per (b, s-chunk of 8).
// Loads S_in into Vsh, normalizes per-capsule in smem (squash), then:
// phase 1: warp (r,hl) computes 8 dots for row s0+r; warps 0..7 softmax.
// phase 2: warp w -> capsule w, atomics into S_out.
// iter==1: S0 -> S1;  iter==2: S1 -> S2 (also writes B_logits).
__global__ __launch_bounds__(512) void pass_kernel(float* __restrict__ out,
                                                   int iter) {
  const int b = blockIdx.x >> 4;
  const int sc = blockIdx.x & 15;
  const int tid = threadIdx.x;
  const int lane = tid & 31;
  const int w = tid >> 5;
  const int s0 = sc * 8;

  __shared__ __align__(16) float Vsh[NCAPS * DCAPS];  // 32 KB
  __shared__ float csh[8][NCAPS];
  __shared__ float dsh[8][NCAPS];

  const float* Sin = (iter == 1) ? &g_S0[(size_t)b * NCAPS * DCAPS]
                                 : &g_S1[(size_t)b * NCAPS * DCAPS];
  {
    const float4* vsrc = (const float4*)Sin;
    float4* vdst = (float4*)Vsh;
#pragma unroll
    for (int j = 0; j < 4; j++) vdst[tid + j * 512] = vsrc[tid + j * 512];
    __syncthreads();
  }

  // ---- in-smem squash: warp w normalizes capsule w ----
  {
    float4* row = (float4*)&Vsh[w * DCAPS];
    float4 v[4];
    float ss = 0.f;
#pragma unroll
    for (int j = 0; j < 4; j++) {
      v[j] = row[lane + j * 32];
      ss += v[j].x * v[j].x + v[j].y * v[j].y + v[j].z * v[j].z + v[j].w * v[j].w;
    }
#pragma unroll
    for (int o = 16; o > 0; o >>= 1) ss += __shfl_xor_sync(0xffffffffu, ss, o);
    const float inv = rsqrtf(ss + EPS);
#pragma unroll
    for (int j = 0; j < 4; j++) {
      v[j].x *= inv; v[j].y *= inv; v[j].z *= inv; v[j].w *= inv;
      row[lane + j * 32] = v[j];
    }
  }
  __syncthreads();

  // ---- phase 1: warp (r, hl) computes 8 dots for row s0+r ----
  {
    const int r = w & 7;
    const int hl = w >> 3;
    const __half* Us = &g_Uh[(size_t)(b * SEQ + s0 + r) * NDIM];
#pragma unroll
    for (int k = 0; k < 8; k++) {
      const int n = hl * 8 + k;
      const uint2* up = (const uint2*)(Us + n * DCAPS);
      float d = 0.f;
#pragma unroll
      for (int j = 0; j < 4; j++) {
        uint2 hv = up[lane + j * 32];  // halves at d = lane*4 + j*128
        float2 f0 = __half22float2(*(__half2*)&hv.x);
        float2 f1 = __half22float2(*(__half2*)&hv.y);
        const float4 vv = *(const float4*)&Vsh[n * DCAPS + lane * 4 + j * 128];
        d = fmaf(f0.x, vv.x, d);
        d = fmaf(f0.y, vv.y, d);
        d = fmaf(f1.x, vv.z, d);
        d = fmaf(f1.y, vv.w, d);
      }
#pragma unroll
      for (int o = 16; o > 0; o >>= 1) d += __shfl_xor_sync(0xffffffffu, d, o);
      if (lane == 0) dsh[r][n] = d;
    }
  }
  __syncthreads();

  // ---- softmax: warps 0..7, row w, lanes 0..15 ----
  if (w < 8) {
    const int s = s0 + w;
    const int bi0 = (b * SEQ + s) * NCAPS;
    float bfull = -1e30f;
    if (lane < NCAPS) {
      bfull = dsh[w][lane] + (iter == 2 ? g_B[bi0 + lane] : 0.f);
      if (iter == 1) g_B[bi0 + lane] = bfull;
      else out[OFF_B + bi0 + lane] = bfull;  // B_logits = B entering last iter
    }
    float mx = bfull;
#pragma unroll
    for (int o = 8; o > 0; o >>= 1) mx = fmaxf(mx, __shfl_xor_sync(0xffffffffu, mx, o));
    float e = (lane < NCAPS) ? expf(bfull - mx) : 0.f;
    float sum = e;
#pragma unroll
    for (int o = 8; o > 0; o >>= 1) sum += __shfl_xor_sync(0xffffffffu, sum, o);
    if (lane < NCAPS) {
      float cc = e / sum;
      csh[w][lane] = cc;
      out[OFF_C + (size_t)((iter * BATCH + b) * SEQ + s) * NCAPS + lane] = cc;
    }
  }
  __syncthreads();

  // ---- phase 2: warp w -> capsule w; atomics into S_out ----
  {
    const int n = w;
    float Sacc[16];
#pragma unroll
    for (int q = 0; q < 16; q++) Sacc[q] = 0.f;
#pragma unroll
    for (int r = 0; r < 8; r++) {
      const float cc = csh[r][n];
      const uint2* up =
          (const uint2*)&g_Uh[((size_t)(b * SEQ + s0 + r) * NCAPS + n) * DCAPS];
#pragma unroll
      for (int j = 0; j < 4; j++) {
        uint2 hv = up[lane + j * 32];
        float2 f0 = __half22float2(*(__half2*)&hv.x);
        float2 f1 = __half22float2(*(__half2*)&hv.y);
        Sacc[j * 4 + 0] = fmaf(cc, f0.x, Sacc[j * 4 + 0]);
        Sacc[j * 4 + 1] = fmaf(cc, f0.y, Sacc[j * 4 + 1]);
        Sacc[j * 4 + 2] = fmaf(cc, f1.x, Sacc[j * 4 + 2]);
        Sacc[j * 4 + 3] = fmaf(cc, f1.y, Sacc[j * 4 + 3]);
      }
    }
    float* Sg = (iter == 1) ? &g_S1[(size_t)(b * NCAPS + n) * DCAPS]
                            : &g_S2[(size_t)(b * NCAPS + n) * DCAPS];
#pragma unroll
    for (int j = 0; j < 4; j++)
#pragma unroll
      for (int q = 0; q < 4; q++)
        atomicAdd(&Sg[lane * 4 + j * 128 + q], Sacc[j * 4 + q]);
  }
}

// final squash: V = S2 * rsqrt(||S2||^2 + eps) -> out; re-zero S1, S2
__global__ __launch_bounds__(512) void squash_final_kernel(float* __restrict__ out) {
  const int bn = blockIdx.x;  // (b*16+n)
  const int tid = threadIdx.x;
  const int lane = tid & 31, warp = tid >> 5;
  __shared__ float wred[16];
  __shared__ float s_inv;

  size_t base = (size_t)bn * DCAPS;
  float s = g_S2[base + tid];
  g_S1[base + tid] = 0.f;
  g_S2[base + tid] = 0.f;
  float sq = s * s;
#pragma unroll
  for (int o = 16; o > 0; o >>= 1) sq += __shfl_xor_sync(0xffffffffu, sq, o);
  if (lane == 0) wred[warp] = sq;
  __syncthreads();
  if (tid == 0) {
    float t = 0.f;
#pragma unroll
    for (int k = 0; k < 16; k++) t += wred[k];
    s_inv = rsqrtf(t + EPS);
  }
  __syncthreads();
  out[OFF_V + base + tid] = s * s_inv;
}

// ---------------------------------------------------------------------------
extern "C" void kernel_launch(void* const* d_in, const int* in_sizes, int n_in,
                              void* d_out, int out_size) {
  const float* x = (const float*)d_in[0];  // (32,128,1024) f32
  const float* W = (const float*)d_in[1];  // (1024,8192) f32
  float* out = (float*)d_out;

  cudaFuncSetAttribute(gemm_hmma_kernel,
                       cudaFuncAttributeMaxDynamicSharedMemorySize, GEMM_SMEM);

  prep_kernel<<<12544, 256>>>(x, W, out);
  gemm_hmma_kernel<<<dim3(NDIM / 128, MDIM / 128), 128, GEMM_SMEM>>>();
  pass_kernel<<<BATCH * 16, 512>>>(out, 1);
  pass_kernel<<<BATCH * 16, 512>>>(out, 2);
  squash_final_kernel<<<BATCH * NCAPS, 512>>>(out);
}